// round 2
// baseline (speedup 1.0000x reference)
#include <cuda_runtime.h>

#define NB    4
#define NSEQ  4096
#define DIM   32
#define CDIM  256

// Scratch (device globals — no allocation allowed in kernel_launch)
__device__ __align__(16) float g_q[NB * NSEQ * DIM];
__device__ __align__(16) float g_k[NB * NSEQ * DIM];
__device__ __align__(16) float g_v[NB * NSEQ * CDIM];
__device__ __align__(16) float g_att[NB * NSEQ * CDIM];

// ---------------------------------------------------------------------------
// Kernel 1: QKV projection.  [16384 x 320] = x[16384 x 256] @ [wq|wk|wv] + bias
// routed into g_q / g_k / g_v.
// Grid: (5 col-tiles of 64, 256 row-tiles of 64), 256 threads, 4x4 per thread.
// ---------------------------------------------------------------------------
__global__ __launch_bounds__(256) void qkv_kernel(
    const float* __restrict__ x,
    const float* __restrict__ wq, const float* __restrict__ bq,
    const float* __restrict__ wk, const float* __restrict__ bk,
    const float* __restrict__ wv, const float* __restrict__ bv)
{
    __shared__ __align__(16) float As[64][33];
    __shared__ __align__(16) float Bs[32][68];

    const int n0 = blockIdx.x * 64;   // output column tile (0..319)
    const int m0 = blockIdx.y * 64;   // row tile
    const int tid = threadIdx.x;
    const int ty = tid >> 4, tx = tid & 15;

    float acc[4][4];
#pragma unroll
    for (int i = 0; i < 4; i++)
#pragma unroll
        for (int j = 0; j < 4; j++) acc[i][j] = 0.f;

    for (int k0 = 0; k0 < CDIM; k0 += 32) {
        // load A tile 64x32 (coalesced)
        for (int i = tid; i < 64 * 32; i += 256) {
            int r = i >> 5, c = i & 31;
            As[r][c] = x[(m0 + r) * CDIM + k0 + c];
        }
        // load W tile 32x64, routed from wq/wk/wv
        for (int i = tid; i < 32 * 64; i += 256) {
            int k = i >> 6, col = i & 63;
            int gc = n0 + col, gk = k0 + k;
            float w;
            if (gc < 32)        w = wq[gk * DIM + gc];
            else if (gc < 64)   w = wk[gk * DIM + (gc - 32)];
            else                w = wv[gk * CDIM + (gc - 64)];
            Bs[k][col] = w;
        }
        __syncthreads();
#pragma unroll
        for (int k = 0; k < 32; k++) {
            float a[4];
#pragma unroll
            for (int i = 0; i < 4; i++) a[i] = As[ty * 4 + i][k];
            float4 b4 = *(const float4*)&Bs[k][tx * 4];
#pragma unroll
            for (int i = 0; i < 4; i++) {
                acc[i][0] += a[i] * b4.x;
                acc[i][1] += a[i] * b4.y;
                acc[i][2] += a[i] * b4.z;
                acc[i][3] += a[i] * b4.w;
            }
        }
        __syncthreads();
    }

#pragma unroll
    for (int i = 0; i < 4; i++) {
        int row = m0 + ty * 4 + i;
#pragma unroll
        for (int j = 0; j < 4; j++) {
            int gc = n0 + tx * 4 + j;
            if (gc < 32)      g_q[row * DIM + gc]            = acc[i][j] + bq[gc];
            else if (gc < 64) g_k[row * DIM + (gc - 32)]     = acc[i][j] + bk[gc - 32];
            else              g_v[row * CDIM + (gc - 64)]    = acc[i][j] + bv[gc - 64];
        }
    }
}

// ---------------------------------------------------------------------------
// Kernel 2: flash attention.
// Grid: (64 q-tiles, 4 batches), 256 threads.
// Thread (ty,tx): rows ty*4..+3 of the 64-row Q tile, cols {ch*64 + tx*4 .. +3}.
// Dynamic smem: Qs[64][33], Ks[64][33], Ps[64][68], Vs[64][256]  (~97.5 KB)
// ---------------------------------------------------------------------------
__global__ __launch_bounds__(256, 2) void attn_kernel()
{
    extern __shared__ __align__(16) float sm[];
    float* Qs = sm;                              // 64*33
    float* Ks = sm + 64 * 33;                    // 64*33
    float* Ps = sm + 2 * 64 * 33;                // 64*68
    float* Vs = sm + 2 * 64 * 33 + 64 * 68;      // 64*256

    const int b  = blockIdx.y;
    const int q0 = blockIdx.x * 64;
    const int tid = threadIdx.x;
    const int ty = tid >> 4, tx = tid & 15;
    const float scale = 0.17677669529663687f;    // 1/sqrt(32)

    // load + pre-scale Q tile
    const float* qg = g_q + (b * NSEQ + q0) * DIM;
    for (int i = tid; i < 64 * DIM; i += 256) {
        int r = i >> 5, d = i & 31;
        Qs[r * 33 + d] = qg[i] * scale;
    }

    float acc[4][4][4];
    float mrow[4], lrow[4];
#pragma unroll
    for (int r = 0; r < 4; r++) {
        mrow[r] = -3.0e38f; lrow[r] = 0.f;
#pragma unroll
        for (int ch = 0; ch < 4; ch++)
#pragma unroll
            for (int c = 0; c < 4; c++) acc[r][ch][c] = 0.f;
    }
    __syncthreads();

    for (int j0 = 0; j0 < NSEQ; j0 += 64) {
        // stage K tile (64x32) and V tile (64x256)
        const float* kg = g_k + (b * NSEQ + j0) * DIM;
        for (int i = tid; i < 64 * DIM; i += 256) {
            int r = i >> 5, d = i & 31;
            Ks[r * 33 + d] = kg[i];
        }
        const float4* vg = (const float4*)(g_v + (b * NSEQ + j0) * CDIM);
        float4* Vs4 = (float4*)Vs;
        for (int i = tid; i < 64 * CDIM / 4; i += 256) Vs4[i] = vg[i];
        __syncthreads();

        // S = Q @ K^T  (thread computes 4x4 sub-tile of the 64x64 S tile)
        float s[4][4];
#pragma unroll
        for (int r = 0; r < 4; r++)
#pragma unroll
            for (int c = 0; c < 4; c++) s[r][c] = 0.f;
#pragma unroll 8
        for (int k = 0; k < DIM; k++) {
            float a[4], bb[4];
#pragma unroll
            for (int r = 0; r < 4; r++) a[r]  = Qs[(ty * 4 + r) * 33 + k];
#pragma unroll
            for (int c = 0; c < 4; c++) bb[c] = Ks[(tx * 4 + c) * 33 + k];
#pragma unroll
            for (int r = 0; r < 4; r++)
#pragma unroll
                for (int c = 0; c < 4; c++) s[r][c] += a[r] * bb[c];
        }

        // online softmax (row reductions across the 16 tx lanes, shfl width 16)
#pragma unroll
        for (int r = 0; r < 4; r++) {
            float mt = fmaxf(fmaxf(s[r][0], s[r][1]), fmaxf(s[r][2], s[r][3]));
#pragma unroll
            for (int off = 8; off >= 1; off >>= 1)
                mt = fmaxf(mt, __shfl_xor_sync(0xffffffffu, mt, off, 16));
            float mnew = fmaxf(mrow[r], mt);
            float alpha = __expf(mrow[r] - mnew);
            float psum = 0.f;
#pragma unroll
            for (int c = 0; c < 4; c++) {
                float p = __expf(s[r][c] - mnew);
                s[r][c] = p;
                psum += p;
            }
#pragma unroll
            for (int off = 8; off >= 1; off >>= 1)
                psum += __shfl_xor_sync(0xffffffffu, psum, off, 16);
            lrow[r] = lrow[r] * alpha + psum;
            mrow[r] = mnew;
#pragma unroll
            for (int ch = 0; ch < 4; ch++)
#pragma unroll
                for (int c = 0; c < 4; c++) acc[r][ch][c] *= alpha;
            *(float4*)&Ps[(ty * 4 + r) * 68 + tx * 4] =
                make_float4(s[r][0], s[r][1], s[r][2], s[r][3]);
        }
        __syncthreads();

        // O += P @ V
#pragma unroll 4
        for (int jj = 0; jj < 64; jj++) {
            float p[4];
#pragma unroll
            for (int r = 0; r < 4; r++) p[r] = Ps[(ty * 4 + r) * 68 + jj];
#pragma unroll
            for (int ch = 0; ch < 4; ch++) {
                float4 v = *(const float4*)&Vs[jj * CDIM + ch * 64 + tx * 4];
#pragma unroll
                for (int r = 0; r < 4; r++) {
                    acc[r][ch][0] += p[r] * v.x;
                    acc[r][ch][1] += p[r] * v.y;
                    acc[r][ch][2] += p[r] * v.z;
                    acc[r][ch][3] += p[r] * v.w;
                }
            }
        }
        __syncthreads();
    }

    // normalize and store attended tile
    float* og = g_att + (b * NSEQ + q0) * CDIM;
#pragma unroll
    for (int r = 0; r < 4; r++) {
        float inv = 1.f / lrow[r];
#pragma unroll
        for (int ch = 0; ch < 4; ch++) {
            float4 o;
            o.x = acc[r][ch][0] * inv;
            o.y = acc[r][ch][1] * inv;
            o.z = acc[r][ch][2] * inv;
            o.w = acc[r][ch][3] * inv;
            *(float4*)&og[(ty * 4 + r) * CDIM + ch * 64 + tx * 4] = o;
        }
    }
}

// ---------------------------------------------------------------------------
// Kernel 3: output projection + residual.
// out[16384x256] = x + g_att @ wo + bo
// ---------------------------------------------------------------------------
__global__ __launch_bounds__(256) void proj_kernel(
    const float* __restrict__ x,
    const float* __restrict__ wo, const float* __restrict__ bo,
    float* __restrict__ out)
{
    __shared__ __align__(16) float As[64][33];
    __shared__ __align__(16) float Bs[32][68];

    const int n0 = blockIdx.x * 64;
    const int m0 = blockIdx.y * 64;
    const int tid = threadIdx.x;
    const int ty = tid >> 4, tx = tid & 15;

    float acc[4][4];
#pragma unroll
    for (int i = 0; i < 4; i++)
#pragma unroll
        for (int j = 0; j < 4; j++) acc[i][j] = 0.f;

    for (int k0 = 0; k0 < CDIM; k0 += 32) {
        for (int i = tid; i < 64 * 32; i += 256) {
            int r = i >> 5, c = i & 31;
            As[r][c] = g_att[(m0 + r) * CDIM + k0 + c];
        }
        for (int i = tid; i < 32 * 64; i += 256) {
            int k = i >> 6, col = i & 63;
            Bs[k][col] = wo[(k0 + k) * CDIM + n0 + col];
        }
        __syncthreads();
#pragma unroll
        for (int k = 0; k < 32; k++) {
            float a[4];
#pragma unroll
            for (int i = 0; i < 4; i++) a[i] = As[ty * 4 + i][k];
            float4 b4 = *(const float4*)&Bs[k][tx * 4];
#pragma unroll
            for (int i = 0; i < 4; i++) {
                acc[i][0] += a[i] * b4.x;
                acc[i][1] += a[i] * b4.y;
                acc[i][2] += a[i] * b4.z;
                acc[i][3] += a[i] * b4.w;
            }
        }
        __syncthreads();
    }

    float4 bo4 = *(const float4*)&bo[n0 + tx * 4];
#pragma unroll
    for (int i = 0; i < 4; i++) {
        int row = m0 + ty * 4 + i;
        float4 x4 = *(const float4*)&x[row * CDIM + n0 + tx * 4];
        float4 o;
        o.x = x4.x + acc[i][0] + bo4.x;
        o.y = x4.y + acc[i][1] + bo4.y;
        o.z = x4.z + acc[i][2] + bo4.z;
        o.w = x4.w + acc[i][3] + bo4.w;
        *(float4*)&out[row * CDIM + n0 + tx * 4] = o;
    }
}

// ---------------------------------------------------------------------------
extern "C" void kernel_launch(void* const* d_in, const int* in_sizes, int n_in,
                              void* d_out, int out_size)
{
    const float* x  = (const float*)d_in[0];
    const float* wq = (const float*)d_in[1];
    const float* bq = (const float*)d_in[2];
    const float* wk = (const float*)d_in[3];
    const float* bk = (const float*)d_in[4];
    const float* wv = (const float*)d_in[5];
    const float* bv = (const float*)d_in[6];
    const float* wo = (const float*)d_in[7];
    const float* bo = (const float*)d_in[8];
    float* out = (float*)d_out;

    // 16384 rows, 320 output cols (q|k|v)
    qkv_kernel<<<dim3(5, 256), 256>>>(x, wq, bq, wk, bk, wv, bv);

    const int ATTN_SMEM = (2 * 64 * 33 + 64 * 68 + 64 * 256) * (int)sizeof(float);
    cudaFuncSetAttribute(attn_kernel,
                         cudaFuncAttributeMaxDynamicSharedMemorySize, ATTN_SMEM);
    attn_kernel<<<dim3(NSEQ / 64, NB), 256, ATTN_SMEM>>>();

    proj_kernel<<<dim3(4, 256), 256>>>(x, wo, bo, out);
}

// round 4
// speedup vs baseline: 1.0655x; 1.0655x over previous
#include <cuda_runtime.h>

#define NB    4
#define NSEQ  4096
#define DIM   32
#define CDIM  256

typedef unsigned long long ull;

// Scratch (device globals — no allocation allowed in kernel_launch)
__device__ __align__(16) float g_q[NB * NSEQ * DIM];
__device__ __align__(16) float g_k[NB * NSEQ * DIM];
__device__ __align__(16) float g_v[NB * NSEQ * CDIM];
__device__ __align__(16) float g_att[NB * NSEQ * CDIM];

// ---- packed f32x2 helpers (Blackwell FFMA2 path) ------------------------
__device__ __forceinline__ ull pk2(float lo, float hi) {
    ull r; asm("mov.b64 %0,{%1,%2};" : "=l"(r) : "f"(lo), "f"(hi)); return r;
}
__device__ __forceinline__ void upk2(ull v, float& lo, float& hi) {
    asm("mov.b64 {%0,%1},%2;" : "=f"(lo), "=f"(hi) : "l"(v));
}
__device__ __forceinline__ ull fma2(ull a, ull b, ull c) {
    ull d; asm("fma.rn.f32x2 %0,%1,%2,%3;" : "=l"(d) : "l"(a), "l"(b), "l"(c)); return d;
}
__device__ __forceinline__ ull mul2(ull a, ull b) {
    ull d; asm("mul.rn.f32x2 %0,%1,%2;" : "=l"(d) : "l"(a), "l"(b)); return d;
}

// ---------------------------------------------------------------------------
// Kernel 1: QKV projection.  [16384 x 320] = x[16384 x 256] @ [wq|wk|wv] + bias
// ---------------------------------------------------------------------------
__global__ __launch_bounds__(256) void qkv_kernel(
    const float* __restrict__ x,
    const float* __restrict__ wq, const float* __restrict__ bq,
    const float* __restrict__ wk, const float* __restrict__ bk,
    const float* __restrict__ wv, const float* __restrict__ bv)
{
    __shared__ __align__(16) float As[64][33];
    __shared__ __align__(16) float Bs[32][68];

    const int n0 = blockIdx.x * 64;
    const int m0 = blockIdx.y * 64;
    const int tid = threadIdx.x;
    const int ty = tid >> 4, tx = tid & 15;

    ull acc2[4][2];
#pragma unroll
    for (int i = 0; i < 4; i++) { acc2[i][0] = 0ull; acc2[i][1] = 0ull; }

    for (int k0 = 0; k0 < CDIM; k0 += 32) {
        for (int i = tid; i < 64 * 32; i += 256) {
            int r = i >> 5, c = i & 31;
            As[r][c] = x[(m0 + r) * CDIM + k0 + c];
        }
        for (int i = tid; i < 32 * 64; i += 256) {
            int k = i >> 6, col = i & 63;
            int gc = n0 + col, gk = k0 + k;
            float w;
            if (gc < 32)        w = wq[gk * DIM + gc];
            else if (gc < 64)   w = wk[gk * DIM + (gc - 32)];
            else                w = wv[gk * CDIM + (gc - 64)];
            Bs[k][col] = w;
        }
        __syncthreads();
#pragma unroll
        for (int k = 0; k < 32; k++) {
            float a0 = As[ty * 4 + 0][k];
            float a1 = As[ty * 4 + 1][k];
            float a2 = As[ty * 4 + 2][k];
            float a3 = As[ty * 4 + 3][k];
            ulonglong2 b2 = *(const ulonglong2*)&Bs[k][tx * 4];
            ull p;
            p = pk2(a0, a0); acc2[0][0] = fma2(p, b2.x, acc2[0][0]); acc2[0][1] = fma2(p, b2.y, acc2[0][1]);
            p = pk2(a1, a1); acc2[1][0] = fma2(p, b2.x, acc2[1][0]); acc2[1][1] = fma2(p, b2.y, acc2[1][1]);
            p = pk2(a2, a2); acc2[2][0] = fma2(p, b2.x, acc2[2][0]); acc2[2][1] = fma2(p, b2.y, acc2[2][1]);
            p = pk2(a3, a3); acc2[3][0] = fma2(p, b2.x, acc2[3][0]); acc2[3][1] = fma2(p, b2.y, acc2[3][1]);
        }
        __syncthreads();
    }

#pragma unroll
    for (int i = 0; i < 4; i++) {
        int row = m0 + ty * 4 + i;
        float v[4];
        upk2(acc2[i][0], v[0], v[1]);
        upk2(acc2[i][1], v[2], v[3]);
#pragma unroll
        for (int j = 0; j < 4; j++) {
            int gc = n0 + tx * 4 + j;
            if (gc < 32)      g_q[row * DIM + gc]         = v[j] + bq[gc];
            else if (gc < 64) g_k[row * DIM + (gc - 32)]  = v[j] + bk[gc - 32];
            else              g_v[row * CDIM + (gc - 64)] = v[j] + bv[gc - 64];
        }
    }
}

// ---------------------------------------------------------------------------
// Kernel 2: flash attention with packed f32x2 FMA.
// Grid: (64 q-tiles, 4 batches), 256 threads, 2 CTAs/SM.
// SMEM: Qt[32][68] (Q transposed, pre-scaled), Kt[32][68] (K transposed),
//       Ps[64][68], Vs[64][256]  -> 100352 B dynamic.
// Thread (ty,tx): rows ty*4..+3, cols {ch*64 + tx*4 .. +3} for ch=0..3.
// ---------------------------------------------------------------------------
__global__ __launch_bounds__(256, 2) void attn_kernel()
{
    extern __shared__ __align__(16) float sm[];
    float* Qt = sm;                        // 32 x 68  (d-major, row minor)
    float* Kt = sm + 32 * 68;              // 32 x 68
    float* Ps = sm + 2 * 32 * 68;          // 64 x 68
    float* Vs = sm + 2 * 32 * 68 + 64 * 68; // 64 x 256

    const int b  = blockIdx.y;
    const int q0 = blockIdx.x * 64;
    const int tid = threadIdx.x;
    const int ty = tid >> 4, tx = tid & 15;
    const float scale = 0.17677669529663687f;    // 1/sqrt(32)

    // stage Q transposed + pre-scaled
    const float* qg = g_q + (b * NSEQ + q0) * DIM;
    for (int i = tid; i < 64 * DIM; i += 256) {
        int r = i >> 5, d = i & 31;
        Qt[d * 68 + r] = qg[i] * scale;
    }

    ull acc2[4][8];
    float mrow[4], lrow[4];
#pragma unroll
    for (int r = 0; r < 4; r++) {
        mrow[r] = -3.0e38f; lrow[r] = 0.f;
#pragma unroll
        for (int p = 0; p < 8; p++) acc2[r][p] = 0ull;
    }
    __syncthreads();

    for (int j0 = 0; j0 < NSEQ; j0 += 64) {
        // stage K transposed (32 x 64) and V (64 x 256)
        const float* kg = g_k + (b * NSEQ + j0) * DIM;
        for (int i = tid; i < 64 * DIM; i += 256) {
            int r = i >> 5, d = i & 31;
            Kt[d * 68 + r] = kg[i];
        }
        const float4* vg = (const float4*)(g_v + (b * NSEQ + j0) * CDIM);
        float4* Vs4 = (float4*)Vs;
        for (int i = tid; i < 64 * CDIM / 4; i += 256) Vs4[i] = vg[i];
        __syncthreads();

        // S = Q @ K^T : thread's 4x4 sub-tile, packed along columns
        ull s2[4][2];
#pragma unroll
        for (int r = 0; r < 4; r++) { s2[r][0] = 0ull; s2[r][1] = 0ull; }
#pragma unroll
        for (int k = 0; k < DIM; k++) {
            float4 a4 = *(const float4*)&Qt[k * 68 + ty * 4];
            ulonglong2 b2 = *(const ulonglong2*)&Kt[k * 68 + tx * 4];
            ull p;
            p = pk2(a4.x, a4.x); s2[0][0] = fma2(p, b2.x, s2[0][0]); s2[0][1] = fma2(p, b2.y, s2[0][1]);
            p = pk2(a4.y, a4.y); s2[1][0] = fma2(p, b2.x, s2[1][0]); s2[1][1] = fma2(p, b2.y, s2[1][1]);
            p = pk2(a4.z, a4.z); s2[2][0] = fma2(p, b2.x, s2[2][0]); s2[2][1] = fma2(p, b2.y, s2[2][1]);
            p = pk2(a4.w, a4.w); s2[3][0] = fma2(p, b2.x, s2[3][0]); s2[3][1] = fma2(p, b2.y, s2[3][1]);
        }

        // online softmax (row reductions across 16 tx lanes)
#pragma unroll
        for (int r = 0; r < 4; r++) {
            float s0, s1, s2f, s3;
            upk2(s2[r][0], s0, s1);
            upk2(s2[r][1], s2f, s3);
            float mt = fmaxf(fmaxf(s0, s1), fmaxf(s2f, s3));
#pragma unroll
            for (int off = 8; off >= 1; off >>= 1)
                mt = fmaxf(mt, __shfl_xor_sync(0xffffffffu, mt, off, 16));
            float mnew = fmaxf(mrow[r], mt);
            float alpha = __expf(mrow[r] - mnew);
            float p0 = __expf(s0 - mnew);
            float p1 = __expf(s1 - mnew);
            float p2 = __expf(s2f - mnew);
            float p3 = __expf(s3 - mnew);
            float psum = (p0 + p1) + (p2 + p3);
#pragma unroll
            for (int off = 8; off >= 1; off >>= 1)
                psum += __shfl_xor_sync(0xffffffffu, psum, off, 16);
            lrow[r] = lrow[r] * alpha + psum;
            mrow[r] = mnew;
            ull a2 = pk2(alpha, alpha);
#pragma unroll
            for (int p = 0; p < 8; p++) acc2[r][p] = mul2(acc2[r][p], a2);
            *(float4*)&Ps[(ty * 4 + r) * 68 + tx * 4] = make_float4(p0, p1, p2, p3);
        }
        __syncthreads();

        // O += P @ V  (packed along columns; V pairs come free from LDS.128)
#pragma unroll 4
        for (int jj = 0; jj < 64; jj++) {
            ull pr[4];
#pragma unroll
            for (int r = 0; r < 4; r++) {
                float pv = Ps[(ty * 4 + r) * 68 + jj];
                pr[r] = pk2(pv, pv);
            }
#pragma unroll
            for (int ch = 0; ch < 4; ch++) {
                ulonglong2 vv = *(const ulonglong2*)&Vs[jj * CDIM + ch * 64 + tx * 4];
#pragma unroll
                for (int r = 0; r < 4; r++) {
                    acc2[r][2 * ch]     = fma2(pr[r], vv.x, acc2[r][2 * ch]);
                    acc2[r][2 * ch + 1] = fma2(pr[r], vv.y, acc2[r][2 * ch + 1]);
                }
            }
        }
        __syncthreads();
    }

    // normalize and store attended tile
    float* og = g_att + (b * NSEQ + q0) * CDIM;
#pragma unroll
    for (int r = 0; r < 4; r++) {
        float inv = 1.f / lrow[r];
        ull inv2 = pk2(inv, inv);
#pragma unroll
        for (int ch = 0; ch < 4; ch++) {
            ull e0 = mul2(acc2[r][2 * ch], inv2);
            ull e1 = mul2(acc2[r][2 * ch + 1], inv2);
            float4 o;
            upk2(e0, o.x, o.y);
            upk2(e1, o.z, o.w);
            *(float4*)&og[(ty * 4 + r) * CDIM + ch * 64 + tx * 4] = o;
        }
    }
}

// ---------------------------------------------------------------------------
// Kernel 3: output projection + residual.
// ---------------------------------------------------------------------------
__global__ __launch_bounds__(256) void proj_kernel(
    const float* __restrict__ x,
    const float* __restrict__ wo, const float* __restrict__ bo,
    float* __restrict__ out)
{
    __shared__ __align__(16) float As[64][33];
    __shared__ __align__(16) float Bs[32][68];

    const int n0 = blockIdx.x * 64;
    const int m0 = blockIdx.y * 64;
    const int tid = threadIdx.x;
    const int ty = tid >> 4, tx = tid & 15;

    ull acc2[4][2];
#pragma unroll
    for (int i = 0; i < 4; i++) { acc2[i][0] = 0ull; acc2[i][1] = 0ull; }

    for (int k0 = 0; k0 < CDIM; k0 += 32) {
        for (int i = tid; i < 64 * 32; i += 256) {
            int r = i >> 5, c = i & 31;
            As[r][c] = g_att[(m0 + r) * CDIM + k0 + c];
        }
        for (int i = tid; i < 32 * 64; i += 256) {
            int k = i >> 6, col = i & 63;
            Bs[k][col] = wo[(k0 + k) * CDIM + n0 + col];
        }
        __syncthreads();
#pragma unroll
        for (int k = 0; k < 32; k++) {
            float a0 = As[ty * 4 + 0][k];
            float a1 = As[ty * 4 + 1][k];
            float a2 = As[ty * 4 + 2][k];
            float a3 = As[ty * 4 + 3][k];
            ulonglong2 b2 = *(const ulonglong2*)&Bs[k][tx * 4];
            ull p;
            p = pk2(a0, a0); acc2[0][0] = fma2(p, b2.x, acc2[0][0]); acc2[0][1] = fma2(p, b2.y, acc2[0][1]);
            p = pk2(a1, a1); acc2[1][0] = fma2(p, b2.x, acc2[1][0]); acc2[1][1] = fma2(p, b2.y, acc2[1][1]);
            p = pk2(a2, a2); acc2[2][0] = fma2(p, b2.x, acc2[2][0]); acc2[2][1] = fma2(p, b2.y, acc2[2][1]);
            p = pk2(a3, a3); acc2[3][0] = fma2(p, b2.x, acc2[3][0]); acc2[3][1] = fma2(p, b2.y, acc2[3][1]);
        }
        __syncthreads();
    }

    float4 bo4 = *(const float4*)&bo[n0 + tx * 4];
#pragma unroll
    for (int i = 0; i < 4; i++) {
        int row = m0 + ty * 4 + i;
        float4 x4 = *(const float4*)&x[row * CDIM + n0 + tx * 4];
        float v[4];
        upk2(acc2[i][0], v[0], v[1]);
        upk2(acc2[i][1], v[2], v[3]);
        float4 o;
        o.x = x4.x + v[0] + bo4.x;
        o.y = x4.y + v[1] + bo4.y;
        o.z = x4.z + v[2] + bo4.z;
        o.w = x4.w + v[3] + bo4.w;
        *(float4*)&out[row * CDIM + n0 + tx * 4] = o;
    }
}

// ---------------------------------------------------------------------------
extern "C" void kernel_launch(void* const* d_in, const int* in_sizes, int n_in,
                              void* d_out, int out_size)
{
    const float* x  = (const float*)d_in[0];
    const float* wq = (const float*)d_in[1];
    const float* bq = (const float*)d_in[2];
    const float* wk = (const float*)d_in[3];
    const float* bk = (const float*)d_in[4];
    const float* wv = (const float*)d_in[5];
    const float* bv = (const float*)d_in[6];
    const float* wo = (const float*)d_in[7];
    const float* bo = (const float*)d_in[8];
    float* out = (float*)d_out;

    qkv_kernel<<<dim3(5, 256), 256>>>(x, wq, bq, wk, bk, wv, bv);

    const int ATTN_SMEM = (2 * 32 * 68 + 64 * 68 + 64 * 256) * (int)sizeof(float);
    cudaFuncSetAttribute(attn_kernel,
                         cudaFuncAttributeMaxDynamicSharedMemorySize, ATTN_SMEM);
    attn_kernel<<<dim3(NSEQ / 64, NB), 256, ATTN_SMEM>>>();

    proj_kernel<<<dim3(4, 256), 256>>>(x, wo, bo, out);
}

// round 5
// speedup vs baseline: 2.1382x; 2.0068x over previous
#include <cuda_runtime.h>

#define NB    4
#define NSEQ  4096
#define DIM   32
#define CDIM  256

typedef unsigned long long ull;

// Scratch (device globals — no allocation allowed in kernel_launch)
__device__ __align__(16) float g_q[NB * NSEQ * DIM];
__device__ __align__(16) float g_k[NB * NSEQ * DIM];
__device__ __align__(16) float g_v[NB * NSEQ * CDIM];
__device__ __align__(16) float g_att[NB * NSEQ * CDIM];

// ---- packed f32x2 helpers (used by the projection kernels) ---------------
__device__ __forceinline__ ull pk2(float lo, float hi) {
    ull r; asm("mov.b64 %0,{%1,%2};" : "=l"(r) : "f"(lo), "f"(hi)); return r;
}
__device__ __forceinline__ void upk2(ull v, float& lo, float& hi) {
    asm("mov.b64 {%0,%1},%2;" : "=f"(lo), "=f"(hi) : "l"(v));
}
__device__ __forceinline__ ull fma2(ull a, ull b, ull c) {
    ull d; asm("fma.rn.f32x2 %0,%1,%2,%3;" : "=l"(d) : "l"(a), "l"(b), "l"(c)); return d;
}

// ---- tf32 warp MMA ------------------------------------------------------
__device__ __forceinline__ void mma_tf32(float* cd, const unsigned* a,
                                         unsigned b0, unsigned b1) {
    asm volatile(
        "mma.sync.aligned.m16n8k8.row.col.f32.tf32.tf32.f32 "
        "{%0,%1,%2,%3},{%4,%5,%6,%7},{%8,%9},{%0,%1,%2,%3};"
        : "+f"(cd[0]), "+f"(cd[1]), "+f"(cd[2]), "+f"(cd[3])
        : "r"(a[0]), "r"(a[1]), "r"(a[2]), "r"(a[3]), "r"(b0), "r"(b1));
}
__device__ __forceinline__ unsigned fbits(float v) { return __float_as_uint(v); }

// ---------------------------------------------------------------------------
// Kernel 1: QKV projection (fp32 exact).
// ---------------------------------------------------------------------------
__global__ __launch_bounds__(256) void qkv_kernel(
    const float* __restrict__ x,
    const float* __restrict__ wq, const float* __restrict__ bq,
    const float* __restrict__ wk, const float* __restrict__ bk,
    const float* __restrict__ wv, const float* __restrict__ bv)
{
    __shared__ __align__(16) float As[64][33];
    __shared__ __align__(16) float Bs[32][68];

    const int n0 = blockIdx.x * 64;
    const int m0 = blockIdx.y * 64;
    const int tid = threadIdx.x;
    const int ty = tid >> 4, tx = tid & 15;

    ull acc2[4][2];
#pragma unroll
    for (int i = 0; i < 4; i++) { acc2[i][0] = 0ull; acc2[i][1] = 0ull; }

    for (int k0 = 0; k0 < CDIM; k0 += 32) {
        for (int i = tid; i < 64 * 32; i += 256) {
            int r = i >> 5, c = i & 31;
            As[r][c] = x[(m0 + r) * CDIM + k0 + c];
        }
        for (int i = tid; i < 32 * 64; i += 256) {
            int k = i >> 6, col = i & 63;
            int gc = n0 + col, gk = k0 + k;
            float w;
            if (gc < 32)        w = wq[gk * DIM + gc];
            else if (gc < 64)   w = wk[gk * DIM + (gc - 32)];
            else                w = wv[gk * CDIM + (gc - 64)];
            Bs[k][col] = w;
        }
        __syncthreads();
#pragma unroll
        for (int k = 0; k < 32; k++) {
            float a0 = As[ty * 4 + 0][k];
            float a1 = As[ty * 4 + 1][k];
            float a2 = As[ty * 4 + 2][k];
            float a3 = As[ty * 4 + 3][k];
            ulonglong2 b2 = *(const ulonglong2*)&Bs[k][tx * 4];
            ull p;
            p = pk2(a0, a0); acc2[0][0] = fma2(p, b2.x, acc2[0][0]); acc2[0][1] = fma2(p, b2.y, acc2[0][1]);
            p = pk2(a1, a1); acc2[1][0] = fma2(p, b2.x, acc2[1][0]); acc2[1][1] = fma2(p, b2.y, acc2[1][1]);
            p = pk2(a2, a2); acc2[2][0] = fma2(p, b2.x, acc2[2][0]); acc2[2][1] = fma2(p, b2.y, acc2[2][1]);
            p = pk2(a3, a3); acc2[3][0] = fma2(p, b2.x, acc2[3][0]); acc2[3][1] = fma2(p, b2.y, acc2[3][1]);
        }
        __syncthreads();
    }

#pragma unroll
    for (int i = 0; i < 4; i++) {
        int row = m0 + ty * 4 + i;
        float v[4];
        upk2(acc2[i][0], v[0], v[1]);
        upk2(acc2[i][1], v[2], v[3]);
#pragma unroll
        for (int j = 0; j < 4; j++) {
            int gc = n0 + tx * 4 + j;
            if (gc < 32)      g_q[row * DIM + gc]         = v[j] + bq[gc];
            else if (gc < 64) g_k[row * DIM + (gc - 32)]  = v[j] + bk[gc - 32];
            else              g_v[row * CDIM + (gc - 64)] = v[j] + bv[gc - 64];
        }
    }
}

// ---------------------------------------------------------------------------
// Kernel 2: flash attention on tensor cores (tf32 HMMA).
// Grid: (32 q-tiles of 128 rows, 4 batches), 256 threads = 8 warps, 1 CTA/SM.
// Warp w owns output rows 16w..16w+15 of the Q tile.
// S = QK^T uses a 2-term hi/lo tf32 split (fp32-accurate scores).
// SMEM: Kth[32][73], Ktl[32][73], Vs[64][264], Ps[128][76]  = 125184 B.
// ---------------------------------------------------------------------------
#define KTP 73
#define VSP 264
#define PSP 76

__global__ __launch_bounds__(256, 1) void attn_kernel()
{
    extern __shared__ __align__(16) float sm[];
    float* Kth = sm;                                   // 32 x 73
    float* Ktl = sm + 32 * KTP;                        // 32 x 73
    float* Vs  = sm + 2 * 32 * KTP;                    // 64 x 264
    float* Ps  = sm + 2 * 32 * KTP + 64 * VSP;         // 128 x 76

    const int b   = blockIdx.y;
    const int q0  = blockIdx.x * 128;
    const int tid = threadIdx.x;
    const int w    = tid >> 5;
    const int lane = tid & 31;
    const int g    = lane >> 2;        // row group 0..7
    const int c    = lane & 3;         // k-col group 0..3
    const float scale = 0.17677669529663687f;   // 1/sqrt(32)

    // ---- preload Q fragments (hi/lo tf32 split, pre-scaled), reused 64x ----
    unsigned qah[4][4], qal[4][4];
    {
        const float* q0p = g_q + (b * NSEQ + q0 + 16 * w + g) * DIM;
        const float* q1p = q0p + 8 * DIM;
#pragma unroll
        for (int ks = 0; ks < 4; ks++) {
            int c0 = 8 * ks + c, c1 = c0 + 4;
            float v; unsigned hb;
            v = q0p[c0] * scale; hb = fbits(v) & 0xFFFFE000u;
            qah[ks][0] = hb; qal[ks][0] = fbits(v - __uint_as_float(hb));
            v = q1p[c0] * scale; hb = fbits(v) & 0xFFFFE000u;
            qah[ks][1] = hb; qal[ks][1] = fbits(v - __uint_as_float(hb));
            v = q0p[c1] * scale; hb = fbits(v) & 0xFFFFE000u;
            qah[ks][2] = hb; qal[ks][2] = fbits(v - __uint_as_float(hb));
            v = q1p[c1] * scale; hb = fbits(v) & 0xFFFFE000u;
            qah[ks][3] = hb; qal[ks][3] = fbits(v - __uint_as_float(hb));
        }
    }

    // output accumulators: 32 n-tiles x 4 (rows g,g+8 ; cols 2c,2c+1)
    float o[32][4];
#pragma unroll
    for (int nt = 0; nt < 32; nt++)
#pragma unroll
        for (int i = 0; i < 4; i++) o[nt][i] = 0.f;
    float m0r = -3.0e38f, m1r = -3.0e38f, l0r = 0.f, l1r = 0.f;

    for (int j0 = 0; j0 < NSEQ; j0 += 64) {
        // ---- stage K (hi/lo, transposed d-major) and V ----
        const float* kg = g_k + (b * NSEQ + j0) * DIM;
        for (int i = tid; i < 64 * DIM; i += 256) {
            int key = i >> 5, d = i & 31;
            float v = kg[i];
            unsigned hb = fbits(v) & 0xFFFFE000u;
            float hf = __uint_as_float(hb);
            Kth[d * KTP + key] = hf;
            Ktl[d * KTP + key] = v - hf;
        }
        const float4* vg = (const float4*)(g_v + (b * NSEQ + j0) * CDIM);
        for (int i = tid; i < 64 * 64; i += 256) {
            int row = i >> 6, cc = i & 63;
            *(float4*)&Vs[row * VSP + cc * 4] = vg[i];
        }
        __syncthreads();

        // ---- S = Q K^T  (split tf32: hh + hl + lh) ----
        float sacc[8][4];
#pragma unroll
        for (int nt = 0; nt < 8; nt++)
#pragma unroll
            for (int i = 0; i < 4; i++) sacc[nt][i] = 0.f;

#pragma unroll
        for (int ks = 0; ks < 4; ks++) {
            const int kd = 8 * ks + c;
            const float* kh0 = &Kth[kd * KTP + g];
            const float* kh1 = &Kth[(kd + 4) * KTP + g];
            const float* kl0 = &Ktl[kd * KTP + g];
            const float* kl1 = &Ktl[(kd + 4) * KTP + g];
#pragma unroll
            for (int nt = 0; nt < 8; nt++) {
                unsigned bh0 = fbits(kh0[8 * nt]);
                unsigned bh1 = fbits(kh1[8 * nt]);
                unsigned bl0 = fbits(kl0[8 * nt]);
                unsigned bl1 = fbits(kl1[8 * nt]);
                mma_tf32(sacc[nt], qah[ks], bh0, bh1);
                mma_tf32(sacc[nt], qah[ks], bl0, bl1);
                mma_tf32(sacc[nt], qal[ks], bh0, bh1);
            }
        }

        // ---- online softmax (rows g and g+8; reduce over 4 lanes) ----
        float mt0 = -3.0e38f, mt1 = -3.0e38f;
#pragma unroll
        for (int nt = 0; nt < 8; nt++) {
            mt0 = fmaxf(mt0, fmaxf(sacc[nt][0], sacc[nt][1]));
            mt1 = fmaxf(mt1, fmaxf(sacc[nt][2], sacc[nt][3]));
        }
        mt0 = fmaxf(mt0, __shfl_xor_sync(0xffffffffu, mt0, 1));
        mt0 = fmaxf(mt0, __shfl_xor_sync(0xffffffffu, mt0, 2));
        mt1 = fmaxf(mt1, __shfl_xor_sync(0xffffffffu, mt1, 1));
        mt1 = fmaxf(mt1, __shfl_xor_sync(0xffffffffu, mt1, 2));
        float mnew0 = fmaxf(m0r, mt0), mnew1 = fmaxf(m1r, mt1);
        float alpha0 = __expf(m0r - mnew0), alpha1 = __expf(m1r - mnew1);

        float ps0 = 0.f, ps1 = 0.f;
#pragma unroll
        for (int nt = 0; nt < 8; nt++) {
            float p0 = __expf(sacc[nt][0] - mnew0);
            float p1 = __expf(sacc[nt][1] - mnew0);
            float p2 = __expf(sacc[nt][2] - mnew1);
            float p3 = __expf(sacc[nt][3] - mnew1);
            sacc[nt][0] = p0; sacc[nt][1] = p1; sacc[nt][2] = p2; sacc[nt][3] = p3;
            ps0 += p0 + p1; ps1 += p2 + p3;
        }
        ps0 += __shfl_xor_sync(0xffffffffu, ps0, 1);
        ps0 += __shfl_xor_sync(0xffffffffu, ps0, 2);
        ps1 += __shfl_xor_sync(0xffffffffu, ps1, 1);
        ps1 += __shfl_xor_sync(0xffffffffu, ps1, 2);
        l0r = l0r * alpha0 + ps0;
        l1r = l1r * alpha1 + ps1;
        m0r = mnew0; m1r = mnew1;

        if (__any_sync(0xffffffffu, (alpha0 != 1.f) | (alpha1 != 1.f))) {
#pragma unroll
            for (int nt = 0; nt < 32; nt++) {
                o[nt][0] *= alpha0; o[nt][1] *= alpha0;
                o[nt][2] *= alpha1; o[nt][3] *= alpha1;
            }
        }

        // ---- write P to SMEM (warp-local) ----
        {
            float* pr0 = &Ps[(16 * w + g) * PSP + 2 * c];
            float* pr1 = pr0 + 8 * PSP;
#pragma unroll
            for (int nt = 0; nt < 8; nt++) {
                *(float2*)&pr0[8 * nt] = make_float2(sacc[nt][0], sacc[nt][1]);
                *(float2*)&pr1[8 * nt] = make_float2(sacc[nt][2], sacc[nt][3]);
            }
        }
        __syncwarp();

        // ---- O += P V  (plain tf32; tf32 truncation in HW) ----
#pragma unroll
        for (int ks = 0; ks < 8; ks++) {
            unsigned pa[4];
            const float* pr0 = &Ps[(16 * w + g) * PSP + 8 * ks + c];
            const float* pr1 = pr0 + 8 * PSP;
            pa[0] = fbits(pr0[0]); pa[2] = fbits(pr0[4]);
            pa[1] = fbits(pr1[0]); pa[3] = fbits(pr1[4]);
            const float* vr0 = &Vs[(8 * ks + c) * VSP + g];
            const float* vr1 = &Vs[(8 * ks + c + 4) * VSP + g];
#pragma unroll
            for (int nt = 0; nt < 32; nt++) {
                unsigned b0 = fbits(vr0[8 * nt]);
                unsigned b1 = fbits(vr1[8 * nt]);
                mma_tf32(o[nt], pa, b0, b1);
            }
        }
        __syncthreads();   // before next tile overwrites Kth/Ktl/Vs
    }

    // ---- normalize + store attended tile ----
    float inv0 = 1.f / l0r, inv1 = 1.f / l1r;
    float* og0 = g_att + (b * NSEQ + q0 + 16 * w + g) * CDIM;
    float* og1 = og0 + 8 * CDIM;
#pragma unroll
    for (int nt = 0; nt < 32; nt++) {
        *(float2*)&og0[8 * nt + 2 * c] = make_float2(o[nt][0] * inv0, o[nt][1] * inv0);
        *(float2*)&og1[8 * nt + 2 * c] = make_float2(o[nt][2] * inv1, o[nt][3] * inv1);
    }
}

// ---------------------------------------------------------------------------
// Kernel 3: output projection + residual (fp32 exact).
// ---------------------------------------------------------------------------
__global__ __launch_bounds__(256) void proj_kernel(
    const float* __restrict__ x,
    const float* __restrict__ wo, const float* __restrict__ bo,
    float* __restrict__ out)
{
    __shared__ __align__(16) float As[64][33];
    __shared__ __align__(16) float Bs[32][68];

    const int n0 = blockIdx.x * 64;
    const int m0 = blockIdx.y * 64;
    const int tid = threadIdx.x;
    const int ty = tid >> 4, tx = tid & 15;

    ull acc2[4][2];
#pragma unroll
    for (int i = 0; i < 4; i++) { acc2[i][0] = 0ull; acc2[i][1] = 0ull; }

    for (int k0 = 0; k0 < CDIM; k0 += 32) {
        for (int i = tid; i < 64 * 32; i += 256) {
            int r = i >> 5, c = i & 31;
            As[r][c] = g_att[(m0 + r) * CDIM + k0 + c];
        }
        for (int i = tid; i < 32 * 64; i += 256) {
            int k = i >> 6, col = i & 63;
            Bs[k][col] = wo[(k0 + k) * CDIM + n0 + col];
        }
        __syncthreads();
#pragma unroll
        for (int k = 0; k < 32; k++) {
            float a0 = As[ty * 4 + 0][k];
            float a1 = As[ty * 4 + 1][k];
            float a2 = As[ty * 4 + 2][k];
            float a3 = As[ty * 4 + 3][k];
            ulonglong2 b2 = *(const ulonglong2*)&Bs[k][tx * 4];
            ull p;
            p = pk2(a0, a0); acc2[0][0] = fma2(p, b2.x, acc2[0][0]); acc2[0][1] = fma2(p, b2.y, acc2[0][1]);
            p = pk2(a1, a1); acc2[1][0] = fma2(p, b2.x, acc2[1][0]); acc2[1][1] = fma2(p, b2.y, acc2[1][1]);
            p = pk2(a2, a2); acc2[2][0] = fma2(p, b2.x, acc2[2][0]); acc2[2][1] = fma2(p, b2.y, acc2[2][1]);
            p = pk2(a3, a3); acc2[3][0] = fma2(p, b2.x, acc2[3][0]); acc2[3][1] = fma2(p, b2.y, acc2[3][1]);
        }
        __syncthreads();
    }

    float4 bo4 = *(const float4*)&bo[n0 + tx * 4];
#pragma unroll
    for (int i = 0; i < 4; i++) {
        int row = m0 + ty * 4 + i;
        float4 x4 = *(const float4*)&x[row * CDIM + n0 + tx * 4];
        float v[4];
        upk2(acc2[i][0], v[0], v[1]);
        upk2(acc2[i][1], v[2], v[3]);
        float4 oo;
        oo.x = x4.x + v[0] + bo4.x;
        oo.y = x4.y + v[1] + bo4.y;
        oo.z = x4.z + v[2] + bo4.z;
        oo.w = x4.w + v[3] + bo4.w;
        *(float4*)&out[row * CDIM + n0 + tx * 4] = oo;
    }
}

// ---------------------------------------------------------------------------
extern "C" void kernel_launch(void* const* d_in, const int* in_sizes, int n_in,
                              void* d_out, int out_size)
{
    const float* x  = (const float*)d_in[0];
    const float* wq = (const float*)d_in[1];
    const float* bq = (const float*)d_in[2];
    const float* wk = (const float*)d_in[3];
    const float* bk = (const float*)d_in[4];
    const float* wv = (const float*)d_in[5];
    const float* bv = (const float*)d_in[6];
    const float* wo = (const float*)d_in[7];
    const float* bo = (const float*)d_in[8];
    float* out = (float*)d_out;

    qkv_kernel<<<dim3(5, 256), 256>>>(x, wq, bq, wk, bk, wv, bv);

    const int ATTN_SMEM = (2 * 32 * KTP + 64 * VSP + 128 * PSP) * (int)sizeof(float);
    cudaFuncSetAttribute(attn_kernel,
                         cudaFuncAttributeMaxDynamicSharedMemorySize, ATTN_SMEM);
    attn_kernel<<<dim3(NSEQ / 128, NB), 256, ATTN_SMEM>>>();

    proj_kernel<<<dim3(4, 256), 256>>>(x, wo, bo, out);
}

// round 7
// speedup vs baseline: 3.5513x; 1.6609x over previous
#include <cuda_runtime.h>
#include <cuda_fp16.h>

#define NB    4
#define NSEQ  4096
#define DIM   32
#define CDIM  256

// Scratch (device globals — no allocation allowed in kernel_launch)
__device__ __align__(16) float g_q[NB * NSEQ * DIM];
__device__ __align__(16) float g_k[NB * NSEQ * DIM];
__device__ __align__(16) float g_v[NB * NSEQ * CDIM];
__device__ __align__(16) float g_att[NB * NSEQ * CDIM];

// ---- fp16 helpers --------------------------------------------------------
// pack two floats to half2 bits: a -> low 16, b -> high 16
__device__ __forceinline__ unsigned f2h2(float a, float b) {
    unsigned r;
    asm("cvt.rn.f16x2.f32 %0,%1,%2;" : "=r"(r) : "f"(b), "f"(a));
    return r;
}
// hi/lo split: v = h + l with h = fp16(v)
__device__ __forceinline__ void splitf(float v, float& h, float& l) {
    __half hh = __float2half_rn(v);
    h = __half2float(hh);
    l = v - h;
}
// fp16 MMA m16n8k16, fp32 accumulate
__device__ __forceinline__ void mma_f16(float* cd, const unsigned* a,
                                        unsigned b0, unsigned b1) {
    asm volatile(
        "mma.sync.aligned.m16n8k16.row.col.f32.f16.f16.f32 "
        "{%0,%1,%2,%3},{%4,%5,%6,%7},{%8,%9},{%0,%1,%2,%3};"
        : "+f"(cd[0]), "+f"(cd[1]), "+f"(cd[2]), "+f"(cd[3])
        : "r"(a[0]), "r"(a[1]), "r"(a[2]), "r"(a[3]), "r"(b0), "r"(b1));
}

// ---------------------------------------------------------------------------
// Kernel 1: QKV projection, fp16 MMA with 2-term hi/lo split (3 products).
// CTA tile: 128 rows x 64 cols, 8 warps (warp = 16 rows x 64 cols).
// SMEM (half2 units): Xh[128*36], Xl[128*36], Wh[32*72], Wl[32*72] = 55296 B.
// grid (5 col-tiles, 128 row-tiles).
// ---------------------------------------------------------------------------
#define XP 36
#define WP 72
#define GEMM_SMEM ((2 * 128 * XP + 2 * 32 * WP) * 4)

__global__ __launch_bounds__(256) void qkv_kernel(
    const float* __restrict__ x,
    const float* __restrict__ wq, const float* __restrict__ bq,
    const float* __restrict__ wk, const float* __restrict__ bk,
    const float* __restrict__ wv, const float* __restrict__ bv)
{
    extern __shared__ unsigned sq[];
    unsigned* Xh = sq;                    // 128 x 36
    unsigned* Xl = sq + 128 * XP;
    unsigned* Wh = sq + 2 * 128 * XP;     // 32 x 72
    unsigned* Wl = sq + 2 * 128 * XP + 32 * WP;

    const int n0  = blockIdx.x * 64;
    const int m0  = blockIdx.y * 128;
    const int tid = threadIdx.x;
    const int w    = tid >> 5;
    const int lane = tid & 31;
    const int g    = lane >> 2;
    const int c    = lane & 3;

    float acc[8][4];
#pragma unroll
    for (int nt = 0; nt < 8; nt++)
#pragma unroll
        for (int i = 0; i < 4; i++) acc[nt][i] = 0.f;

    for (int k0 = 0; k0 < CDIM; k0 += 64) {
        // stage X chunk 128 x 64 as hi/lo half2
        for (int i = tid; i < 128 * 32; i += 256) {
            int kk = i & 31, row = i >> 5;
            float2 xv = *(const float2*)&x[(m0 + row) * CDIM + k0 + 2 * kk];
            float h0, l0, h1, l1;
            splitf(xv.x, h0, l0); splitf(xv.y, h1, l1);
            Xh[row * XP + kk] = f2h2(h0, h1);
            Xl[row * XP + kk] = f2h2(l0, l1);
        }
        // stage W chunk 64 x 64 (routed) as hi/lo half2 (k-pairs packed)
        for (int i = tid; i < 32 * 64; i += 256) {
            int col = i & 63, kk = i >> 6;
            int gk = k0 + 2 * kk, gc = n0 + col;
            float w0, w1;
            if (gc < 32)      { w0 = wq[gk * DIM + gc];        w1 = wq[(gk + 1) * DIM + gc]; }
            else if (gc < 64) { w0 = wk[gk * DIM + gc - 32];   w1 = wk[(gk + 1) * DIM + gc - 32]; }
            else              { w0 = wv[gk * CDIM + gc - 64];  w1 = wv[(gk + 1) * CDIM + gc - 64]; }
            float h0, l0, h1, l1;
            splitf(w0, h0, l0); splitf(w1, h1, l1);
            Wh[kk * WP + col] = f2h2(h0, h1);
            Wl[kk * WP + col] = f2h2(l0, l1);
        }
        __syncthreads();

        const int rg = 16 * w + g;
#pragma unroll
        for (int ks = 0; ks < 4; ks++) {
            unsigned ah[4], al[4];
            ah[0] = Xh[rg * XP + 8 * ks + c];
            ah[1] = Xh[(rg + 8) * XP + 8 * ks + c];
            ah[2] = Xh[rg * XP + 8 * ks + c + 4];
            ah[3] = Xh[(rg + 8) * XP + 8 * ks + c + 4];
            al[0] = Xl[rg * XP + 8 * ks + c];
            al[1] = Xl[(rg + 8) * XP + 8 * ks + c];
            al[2] = Xl[rg * XP + 8 * ks + c + 4];
            al[3] = Xl[(rg + 8) * XP + 8 * ks + c + 4];
#pragma unroll
            for (int nt = 0; nt < 8; nt++) {
                unsigned bh0 = Wh[(8 * ks + c) * WP + 8 * nt + g];
                unsigned bh1 = Wh[(8 * ks + c + 4) * WP + 8 * nt + g];
                unsigned bl0 = Wl[(8 * ks + c) * WP + 8 * nt + g];
                unsigned bl1 = Wl[(8 * ks + c + 4) * WP + 8 * nt + g];
                mma_f16(acc[nt], ah, bh0, bh1);
                mma_f16(acc[nt], al, bh0, bh1);
                mma_f16(acc[nt], ah, bl0, bl1);
            }
        }
        __syncthreads();
    }

    // epilogue: bias + route
    const int r0 = m0 + 16 * w + g, r1 = r0 + 8;
#pragma unroll
    for (int nt = 0; nt < 8; nt++) {
        int gc = n0 + 8 * nt + 2 * c;
        if (gc < 32) {
            float b0 = bq[gc], b1 = bq[gc + 1];
            *(float2*)&g_q[r0 * DIM + gc] = make_float2(acc[nt][0] + b0, acc[nt][1] + b1);
            *(float2*)&g_q[r1 * DIM + gc] = make_float2(acc[nt][2] + b0, acc[nt][3] + b1);
        } else if (gc < 64) {
            int kc = gc - 32;
            float b0 = bk[kc], b1 = bk[kc + 1];
            *(float2*)&g_k[r0 * DIM + kc] = make_float2(acc[nt][0] + b0, acc[nt][1] + b1);
            *(float2*)&g_k[r1 * DIM + kc] = make_float2(acc[nt][2] + b0, acc[nt][3] + b1);
        } else {
            int vc = gc - 64;
            float b0 = bv[vc], b1 = bv[vc + 1];
            *(float2*)&g_v[r0 * CDIM + vc] = make_float2(acc[nt][0] + b0, acc[nt][1] + b1);
            *(float2*)&g_v[r1 * CDIM + vc] = make_float2(acc[nt][2] + b0, acc[nt][3] + b1);
        }
    }
}

// ---------------------------------------------------------------------------
// Kernel 2: flash attention on fp16 tensor cores.
// Grid: (32 q-tiles of 128 rows, 4 batches), 256 threads = 8 warps.
// QK^T: 2-term hi/lo fp16 split (3 mma terms). PV: 1-term fp16.
// SMEM (half2 units): Kth[16*72], Ktl[16*72], Vs[32*264], Ps[128*36] = 61440 B.
// ---------------------------------------------------------------------------
#define KTP 72
#define VSP 264
#define PSP 36
#define ATTN_SMEM ((2 * 16 * KTP + 32 * VSP + 128 * PSP) * 4)

__global__ __launch_bounds__(256, 1) void attn_kernel()
{
    extern __shared__ unsigned sa[];
    unsigned* Kth = sa;                                  // 16 x 72
    unsigned* Ktl = sa + 16 * KTP;                       // 16 x 72
    unsigned* Vs  = sa + 2 * 16 * KTP;                   // 32 x 264
    unsigned* Ps  = sa + 2 * 16 * KTP + 32 * VSP;        // 128 x 36

    const int b   = blockIdx.y;
    const int q0  = blockIdx.x * 128;
    const int tid = threadIdx.x;
    const int w    = tid >> 5;
    const int lane = tid & 31;
    const int g    = lane >> 2;
    const int c    = lane & 3;
    const float scale = 0.17677669529663687f;   // 1/sqrt(32)

    // ---- preload Q fragments (hi/lo fp16, pre-scaled), reused 64x ----
    unsigned qah[2][4], qal[2][4];
    {
        const float* q0p = g_q + (b * NSEQ + q0 + 16 * w + g) * DIM;
        const float* q1p = q0p + 8 * DIM;
#pragma unroll
        for (int ks = 0; ks < 2; ks++) {
            int k0 = 16 * ks + 2 * c;
            float h0, l0, h1, l1;
#pragma unroll
            for (int part = 0; part < 4; part++) {
                const float* qp = (part & 1) ? q1p : q0p;
                int kk = k0 + ((part & 2) ? 8 : 0);
                splitf(qp[kk] * scale, h0, l0);
                splitf(qp[kk + 1] * scale, h1, l1);
                qah[ks][part] = f2h2(h0, h1);
                qal[ks][part] = f2h2(l0, l1);
            }
        }
    }

    float o[32][4];
#pragma unroll
    for (int nt = 0; nt < 32; nt++)
#pragma unroll
        for (int i = 0; i < 4; i++) o[nt][i] = 0.f;
    float m0r = -3.0e38f, m1r = -3.0e38f, l0r = 0.f, l1r = 0.f;

    for (int j0 = 0; j0 < NSEQ; j0 += 64) {
        // ---- stage K (hi/lo, d-pair-packed, transposed) ----
        const float* kg = g_k + (b * NSEQ + j0) * DIM;
        for (int i = tid; i < 64 * 16; i += 256) {
            int dd = i & 15, key = i >> 4;
            float2 kv = *(const float2*)&kg[key * DIM + 2 * dd];
            float h0, l0, h1, l1;
            splitf(kv.x, h0, l0); splitf(kv.y, h1, l1);
            Kth[dd * KTP + key] = f2h2(h0, h1);
            Ktl[dd * KTP + key] = f2h2(l0, l1);
        }
        // ---- stage V (fp16, key-pair-packed) ----
        {
            const float4* vg = (const float4*)(g_v + (b * NSEQ + j0) * CDIM);
            for (int i = tid; i < 32 * 64; i += 256) {
                int kk = i >> 6, c4 = (i & 63);
                float4 va = vg[(2 * kk) * 64 + c4];
                float4 vb = vg[(2 * kk + 1) * 64 + c4];
                uint4 pk;
                pk.x = f2h2(va.x, vb.x);
                pk.y = f2h2(va.y, vb.y);
                pk.z = f2h2(va.z, vb.z);
                pk.w = f2h2(va.w, vb.w);
                *(uint4*)&Vs[kk * VSP + 4 * c4] = pk;
            }
        }
        __syncthreads();

        // ---- S = Q K^T (3-term fp16 split) ----
        float sacc[8][4];
#pragma unroll
        for (int nt = 0; nt < 8; nt++)
#pragma unroll
            for (int i = 0; i < 4; i++) sacc[nt][i] = 0.f;

#pragma unroll
        for (int ks = 0; ks < 2; ks++) {
            const unsigned* kh0 = &Kth[(8 * ks + c) * KTP + g];
            const unsigned* kh1 = &Kth[(8 * ks + c + 4) * KTP + g];
            const unsigned* kl0 = &Ktl[(8 * ks + c) * KTP + g];
            const unsigned* kl1 = &Ktl[(8 * ks + c + 4) * KTP + g];
#pragma unroll
            for (int nt = 0; nt < 8; nt++) {
                unsigned bh0 = kh0[8 * nt];
                unsigned bh1 = kh1[8 * nt];
                unsigned bl0 = kl0[8 * nt];
                unsigned bl1 = kl1[8 * nt];
                mma_f16(sacc[nt], qah[ks], bh0, bh1);
                mma_f16(sacc[nt], qal[ks], bh0, bh1);
                mma_f16(sacc[nt], qah[ks], bl0, bl1);
            }
        }

        // ---- online softmax (rows g and g+8; reduce over 4 lanes) ----
        float mt0 = -3.0e38f, mt1 = -3.0e38f;
#pragma unroll
        for (int nt = 0; nt < 8; nt++) {
            mt0 = fmaxf(mt0, fmaxf(sacc[nt][0], sacc[nt][1]));
            mt1 = fmaxf(mt1, fmaxf(sacc[nt][2], sacc[nt][3]));
        }
        mt0 = fmaxf(mt0, __shfl_xor_sync(0xffffffffu, mt0, 1));
        mt0 = fmaxf(mt0, __shfl_xor_sync(0xffffffffu, mt0, 2));
        mt1 = fmaxf(mt1, __shfl_xor_sync(0xffffffffu, mt1, 1));
        mt1 = fmaxf(mt1, __shfl_xor_sync(0xffffffffu, mt1, 2));
        float mnew0 = fmaxf(m0r, mt0), mnew1 = fmaxf(m1r, mt1);
        float alpha0 = __expf(m0r - mnew0), alpha1 = __expf(m1r - mnew1);

        float ps0 = 0.f, ps1 = 0.f;
#pragma unroll
        for (int nt = 0; nt < 8; nt++) {
            float p0 = __expf(sacc[nt][0] - mnew0);
            float p1 = __expf(sacc[nt][1] - mnew0);
            float p2 = __expf(sacc[nt][2] - mnew1);
            float p3 = __expf(sacc[nt][3] - mnew1);
            ps0 += p0 + p1; ps1 += p2 + p3;
            // write P as fp16 pairs (cols 8nt+2c, 8nt+2c+1 -> kk = 4nt + c)
            Ps[(16 * w + g) * PSP + 4 * nt + c]     = f2h2(p0, p1);
            Ps[(16 * w + g + 8) * PSP + 4 * nt + c] = f2h2(p2, p3);
        }
        ps0 += __shfl_xor_sync(0xffffffffu, ps0, 1);
        ps0 += __shfl_xor_sync(0xffffffffu, ps0, 2);
        ps1 += __shfl_xor_sync(0xffffffffu, ps1, 1);
        ps1 += __shfl_xor_sync(0xffffffffu, ps1, 2);
        l0r = l0r * alpha0 + ps0;
        l1r = l1r * alpha1 + ps1;
        m0r = mnew0; m1r = mnew1;

        if (__any_sync(0xffffffffu, (alpha0 != 1.f) | (alpha1 != 1.f))) {
#pragma unroll
            for (int nt = 0; nt < 32; nt++) {
                o[nt][0] *= alpha0; o[nt][1] *= alpha0;
                o[nt][2] *= alpha1; o[nt][3] *= alpha1;
            }
        }
        __syncwarp();

        // ---- O += P V (fp16) ----
#pragma unroll
        for (int ks = 0; ks < 4; ks++) {
            unsigned pa[4];
            pa[0] = Ps[(16 * w + g) * PSP + 8 * ks + c];
            pa[1] = Ps[(16 * w + g + 8) * PSP + 8 * ks + c];
            pa[2] = Ps[(16 * w + g) * PSP + 8 * ks + c + 4];
            pa[3] = Ps[(16 * w + g + 8) * PSP + 8 * ks + c + 4];
            const unsigned* vr0 = &Vs[(8 * ks + c) * VSP + g];
            const unsigned* vr1 = &Vs[(8 * ks + c + 4) * VSP + g];
#pragma unroll
            for (int nt = 0; nt < 32; nt++) {
                unsigned b0 = vr0[8 * nt];
                unsigned b1 = vr1[8 * nt];
                mma_f16(o[nt], pa, b0, b1);
            }
        }
        __syncthreads();   // before next tile overwrites Kth/Ktl/Vs
    }

    // ---- normalize + store attended tile ----
    float inv0 = 1.f / l0r, inv1 = 1.f / l1r;
    float* og0 = g_att + (b * NSEQ + q0 + 16 * w + g) * CDIM;
    float* og1 = og0 + 8 * CDIM;
#pragma unroll
    for (int nt = 0; nt < 32; nt++) {
        *(float2*)&og0[8 * nt + 2 * c] = make_float2(o[nt][0] * inv0, o[nt][1] * inv0);
        *(float2*)&og1[8 * nt + 2 * c] = make_float2(o[nt][2] * inv1, o[nt][3] * inv1);
    }
}

// ---------------------------------------------------------------------------
// Kernel 3: output projection + residual, fp16 MMA 2-term split.
// Same skeleton as qkv_kernel; grid (4 col-tiles, 128 row-tiles).
// ---------------------------------------------------------------------------
__global__ __launch_bounds__(256) void proj_kernel(
    const float* __restrict__ x,
    const float* __restrict__ wo, const float* __restrict__ bo,
    float* __restrict__ out)
{
    extern __shared__ unsigned sp[];
    unsigned* Xh = sp;
    unsigned* Xl = sp + 128 * XP;
    unsigned* Wh = sp + 2 * 128 * XP;
    unsigned* Wl = sp + 2 * 128 * XP + 32 * WP;

    const int n0  = blockIdx.x * 64;
    const int m0  = blockIdx.y * 128;
    const int tid = threadIdx.x;
    const int w    = tid >> 5;
    const int lane = tid & 31;
    const int g    = lane >> 2;
    const int c    = lane & 3;

    float acc[8][4];
#pragma unroll
    for (int nt = 0; nt < 8; nt++)
#pragma unroll
        for (int i = 0; i < 4; i++) acc[nt][i] = 0.f;

    for (int k0 = 0; k0 < CDIM; k0 += 64) {
        for (int i = tid; i < 128 * 32; i += 256) {
            int kk = i & 31, row = i >> 5;
            float2 xv = *(const float2*)&g_att[(m0 + row) * CDIM + k0 + 2 * kk];
            float h0, l0, h1, l1;
            splitf(xv.x, h0, l0); splitf(xv.y, h1, l1);
            Xh[row * XP + kk] = f2h2(h0, h1);
            Xl[row * XP + kk] = f2h2(l0, l1);
        }
        for (int i = tid; i < 32 * 64; i += 256) {
            int col = i & 63, kk = i >> 6;
            int gk = k0 + 2 * kk, gc = n0 + col;
            float w0 = wo[gk * CDIM + gc];
            float w1 = wo[(gk + 1) * CDIM + gc];
            float h0, l0, h1, l1;
            splitf(w0, h0, l0); splitf(w1, h1, l1);
            Wh[kk * WP + col] = f2h2(h0, h1);
            Wl[kk * WP + col] = f2h2(l0, l1);
        }
        __syncthreads();

        const int rg = 16 * w + g;
#pragma unroll
        for (int ks = 0; ks < 4; ks++) {
            unsigned ah[4], al[4];
            ah[0] = Xh[rg * XP + 8 * ks + c];
            ah[1] = Xh[(rg + 8) * XP + 8 * ks + c];
            ah[2] = Xh[rg * XP + 8 * ks + c + 4];
            ah[3] = Xh[(rg + 8) * XP + 8 * ks + c + 4];
            al[0] = Xl[rg * XP + 8 * ks + c];
            al[1] = Xl[(rg + 8) * XP + 8 * ks + c];
            al[2] = Xl[rg * XP + 8 * ks + c + 4];
            al[3] = Xl[(rg + 8) * XP + 8 * ks + c + 4];
#pragma unroll
            for (int nt = 0; nt < 8; nt++) {
                unsigned bh0 = Wh[(8 * ks + c) * WP + 8 * nt + g];
                unsigned bh1 = Wh[(8 * ks + c + 4) * WP + 8 * nt + g];
                unsigned bl0 = Wl[(8 * ks + c) * WP + 8 * nt + g];
                unsigned bl1 = Wl[(8 * ks + c + 4) * WP + 8 * nt + g];
                mma_f16(acc[nt], ah, bh0, bh1);
                mma_f16(acc[nt], al, bh0, bh1);
                mma_f16(acc[nt], ah, bl0, bl1);
            }
        }
        __syncthreads();
    }

    const int r0 = m0 + 16 * w + g, r1 = r0 + 8;
#pragma unroll
    for (int nt = 0; nt < 8; nt++) {
        int gc = n0 + 8 * nt + 2 * c;
        float b0 = bo[gc], b1 = bo[gc + 1];
        float2 x0 = *(const float2*)&x[r0 * CDIM + gc];
        float2 x1 = *(const float2*)&x[r1 * CDIM + gc];
        *(float2*)&out[r0 * CDIM + gc] =
            make_float2(x0.x + acc[nt][0] + b0, x0.y + acc[nt][1] + b1);
        *(float2*)&out[r1 * CDIM + gc] =
            make_float2(x1.x + acc[nt][2] + b0, x1.y + acc[nt][3] + b1);
    }
}

// ---------------------------------------------------------------------------
extern "C" void kernel_launch(void* const* d_in, const int* in_sizes, int n_in,
                              void* d_out, int out_size)
{
    const float* x  = (const float*)d_in[0];
    const float* wq = (const float*)d_in[1];
    const float* bq = (const float*)d_in[2];
    const float* wk = (const float*)d_in[3];
    const float* bk = (const float*)d_in[4];
    const float* wv = (const float*)d_in[5];
    const float* bv = (const float*)d_in[6];
    const float* wo = (const float*)d_in[7];
    const float* bo = (const float*)d_in[8];
    float* out = (float*)d_out;

    cudaFuncSetAttribute(qkv_kernel,
                         cudaFuncAttributeMaxDynamicSharedMemorySize, GEMM_SMEM);
    cudaFuncSetAttribute(proj_kernel,
                         cudaFuncAttributeMaxDynamicSharedMemorySize, GEMM_SMEM);
    cudaFuncSetAttribute(attn_kernel,
                         cudaFuncAttributeMaxDynamicSharedMemorySize, ATTN_SMEM);

    qkv_kernel<<<dim3(5, 128), 256, GEMM_SMEM>>>(x, wq, bq, wk, bk, wv, bv);
    attn_kernel<<<dim3(NSEQ / 128, NB), 256, ATTN_SMEM>>>();
    proj_kernel<<<dim3(4, 128), 256, GEMM_SMEM>>>(x, wo, bo, out);
}